// round 11
// baseline (speedup 1.0000x reference)
#include <cuda_runtime.h>

#define NP 300000
#define NC 10000
#define MAINT 320

// ---- scratch (device globals; zero-initialized at module load) ----
__device__ int g_count[NC];          // re-zeroed by scan_kernel after use
__device__ int g_offsets[NC + 1];
__device__ unsigned g_packed[NP];    // (center<<18)|(species<<16)|rank
__device__ unsigned g_order[NP];     // (pair_index<<2)|species

// ---------------------------------------------------------------------------
// Histogram with fused int64/int32 detection. Odd 32-bit words of int64 index
// data (values < 2^31) are all zero; for int32 species values 0..3 the odds
// of 256 sampled words all being zero are 4^-256. The atomicAdd return value
// is the pair's rank within its center, so the scatter pass needs no atomics.
// ---------------------------------------------------------------------------
__global__ void hist_kernel(const int* __restrict__ dens,
                            const int* __restrict__ sp) {
    __shared__ int s_any;
    if (threadIdx.x == 0) s_any = 0;
    __syncthreads();
    if (threadIdx.x < 256) {
        int v = sp[2 * threadIdx.x + 1];
        if (v) atomicOr(&s_any, 1);
    }
    __syncthreads();
    int st = s_any ? 1 : 2;   // any nonzero odd word -> int32 (stride 1)

    int p = blockIdx.x * blockDim.x + threadIdx.x;
    if (p < NP) {
        int c = dens[p * st];
        int s = sp[p * st] & 3;
        unsigned rank = (unsigned)atomicAdd(&g_count[c], 1);
        g_packed[p] = ((unsigned)c << 18) | ((unsigned)s << 16) | rank;
    }
}

// ---------------------------------------------------------------------------
// Single-block exclusive scan over 10k counts; re-zeros g_count for the next
// graph replay (device globals are only auto-zeroed at module load).
// ---------------------------------------------------------------------------
__global__ __launch_bounds__(1024) void scan_kernel() {
    __shared__ int sc[NC];
    __shared__ int wsum[32];
    int t = threadIdx.x;
    for (int i = t; i < NC; i += 1024) sc[i] = g_count[i];
    __syncthreads();

    const int PER = (NC + 1023) / 1024;  // 10
    int base = t * PER;
    int local[PER];
    int sum = 0;
#pragma unroll
    for (int k = 0; k < PER; k++) {
        int i = base + k;
        int c = (i < NC) ? sc[i] : 0;
        local[k] = c;
        sum += c;
    }
    int lane = t & 31, warp = t >> 5;
    int inc = sum;
#pragma unroll
    for (int off = 1; off < 32; off <<= 1) {
        int n = __shfl_up_sync(0xffffffffu, inc, off);
        if (lane >= off) inc += n;
    }
    if (lane == 31) wsum[warp] = inc;
    __syncthreads();
    if (warp == 0) {
        int v = wsum[lane];
#pragma unroll
        for (int off = 1; off < 32; off <<= 1) {
            int n = __shfl_up_sync(0xffffffffu, v, off);
            if (lane >= off) v += n;
        }
        wsum[lane] = v;
    }
    __syncthreads();
    int run = inc - sum + (warp ? wsum[warp - 1] : 0);
#pragma unroll
    for (int k = 0; k < PER; k++) {
        int i = base + k;
        if (i < NC) {
            sc[i] = run;
            run += local[k];
        }
    }
    __syncthreads();
    for (int i = t; i < NC; i += 1024) {
        g_offsets[i] = sc[i];
        g_count[i] = 0;   // ready for next replay's hist
    }
    if (t == 1023) g_offsets[NC] = run;
}

// ---------------------------------------------------------------------------
// Atomic-free scatter: position = offsets[center] + rank (rank from hist).
// ---------------------------------------------------------------------------
__global__ void scatter_kernel() {
    int p = blockIdx.x * blockDim.x + threadIdx.x;
    if (p < NP) {
        unsigned e = g_packed[p];
        int c = e >> 18;
        int pos = g_offsets[c] + (int)(e & 0xFFFFu);
        g_order[pos] = ((unsigned)p << 2) | ((e >> 16) & 3u);
    }
}

// ---------------------------------------------------------------------------
// Predicated paired accumulate: if (sv == K) { a01 += v01; a23 += v23 } using
// sm_103a packed f32x2 adds (PTX-only; ptxas never auto-fuses). 3 issue slots
// per species instead of 1 ISETP + 4 FADD. Rounding identical to scalar FADD.
// ---------------------------------------------------------------------------
#define ACC1(K, sv, vx, vy, a01, a23)                                        \
    asm("{\n\t.reg .pred p;\n\t"                                             \
        "setp.eq.s32 p, %2, " #K ";\n\t"                                     \
        "@p add.rn.f32x2 %0, %0, %3;\n\t"                                    \
        "@p add.rn.f32x2 %1, %1, %4;\n\t}"                                   \
        : "+l"(a01), "+l"(a23)                                               \
        : "r"(sv), "l"(vx), "l"(vy))

#define ACC4(sv, v)                                                          \
    do {                                                                     \
        ACC1(0, sv, (v).x, (v).y, a01[0], a23[0]);                           \
        ACC1(1, sv, (v).x, (v).y, a01[1], a23[1]);                           \
        ACC1(2, sv, (v).x, (v).y, a01[2], a23[2]);                           \
        ACC1(3, sv, (v).x, (v).y, a01[3], a23[3]);                           \
    } while (0)

// ---------------------------------------------------------------------------
// Main kernel (R10 structure + f32x2 accumulate + 32-bit addressing): one CTA
// per center, 320 threads = 4 groups of 80. Each group's 80 16-byte slots
// cover the 320-float pair row (l0: 0-4, l1: 5-19, l2: 20-44, l3: 45-79).
// Groups take even quarters of the center's pair range; 4 pairs in flight per
// thread; per-species accumulation via predicated f32x2 adds; then 4-group
// reduce + W-combine + coalesced store.
// ---------------------------------------------------------------------------
__global__ __launch_bounds__(MAINT, 4) void main_kernel(
    const float* __restrict__ v0, const float* __restrict__ v1,
    const float* __restrict__ v2, const float* __restrict__ v3,
    const float* __restrict__ W, float* __restrict__ out) {
    __shared__ float acc[16 * 320];  // [group*4+species][320]
    __shared__ float sW[16];
    int tid = threadIdx.x;
    if (tid < 16) sW[tid] = W[tid];
    int center = blockIdx.x;
    int start = g_offsets[center];
    int end = g_offsets[center + 1];

    int g = tid / 80;
    int slot = tid - g * 80;

    // byte-granular base + row stride (largest array 168 MB -> 32-bit offsets)
    const char* base;
    unsigned rowb, locb;
    if (slot < 5)       { base = (const char*)v0; rowb = 80;  locb = slot * 16u; }
    else if (slot < 20) { base = (const char*)v1; rowb = 240; locb = (slot - 5) * 16u; }
    else if (slot < 45) { base = (const char*)v2; rowb = 400; locb = (slot - 20) * 16u; }
    else                { base = (const char*)v3; rowb = 560; locb = (slot - 45) * 16u; }

    unsigned long long a01[4] = {0ull, 0ull, 0ull, 0ull};
    unsigned long long a23[4] = {0ull, 0ull, 0ull, 0ull};

    int len = end - start;
    int q = len >> 2, rem = len & 3;
    int b0 = start + g * q + min(g, rem);
    int b1 = b0 + q + (g < rem ? 1 : 0);

    int j = b0;
    for (; j + 3 < b1; j += 4) {
        unsigned e0 = g_order[j];
        unsigned e1 = g_order[j + 1];
        unsigned e2 = g_order[j + 2];
        unsigned e3 = g_order[j + 3];
        ulonglong2 va = __ldg((const ulonglong2*)(base + ((e0 >> 2) * rowb + locb)));
        ulonglong2 vb = __ldg((const ulonglong2*)(base + ((e1 >> 2) * rowb + locb)));
        ulonglong2 vc = __ldg((const ulonglong2*)(base + ((e2 >> 2) * rowb + locb)));
        ulonglong2 vd = __ldg((const ulonglong2*)(base + ((e3 >> 2) * rowb + locb)));
        int s0 = e0 & 3, s1 = e1 & 3, s2 = e2 & 3, s3 = e3 & 3;
        ACC4(s0, va);
        ACC4(s1, vb);
        ACC4(s2, vc);
        ACC4(s3, vd);
    }
    for (; j < b1; j++) {
        unsigned e0 = g_order[j];
        ulonglong2 va = __ldg((const ulonglong2*)(base + ((e0 >> 2) * rowb + locb)));
        int s0 = e0 & 3;
        ACC4(s0, va);
    }

    ulonglong2* accv = (ulonglong2*)acc;
#pragma unroll
    for (int s = 0; s < 4; s++)
        accv[(g * 4 + s) * 80 + slot] = make_ulonglong2(a01[s], a23[s]);
    __syncthreads();

    // W-combine + coalesced store: 1280 outputs, 4 per thread.
    float* outc = out + (size_t)center * 1280;
    for (int o = tid; o < 1280; o += MAINT) {
        int l = (o >= 80) + (o >= 320) + (o >= 720);
        int off_out = (l == 0) ? 0 : (l == 1) ? 80 : (l == 2) ? 320 : 720;
        int off_in  = (l == 0) ? 0 : (l == 1) ? 20 : (l == 2) ? 80 : 180;
        int i = o - off_out;
        int n = i % 20;
        int d = (i / 20) & 3;
        int c = i / 80;
        int e = off_in + c * 20 + n;
        float sum = 0.f;
#pragma unroll
        for (int s = 0; s < 4; s++) {
            float a = acc[s * 320 + e] + acc[(4 + s) * 320 + e] +
                      acc[(8 + s) * 320 + e] + acc[(12 + s) * 320 + e];
            sum = fmaf(sW[d * 4 + s], a, sum);
        }
        outc[o] = sum;
    }
}

extern "C" void kernel_launch(void* const* d_in, const int* in_sizes, int n_in,
                              void* d_out, int out_size) {
    const float* v0 = (const float*)d_in[0];
    const float* v1 = (const float*)d_in[1];
    const float* v2 = (const float*)d_in[2];
    const float* v3 = (const float*)d_in[3];
    const float* W = (const float*)d_in[4];
    const int* sp = (const int*)d_in[5];
    const int* dens = (const int*)d_in[6];
    float* out = (float*)d_out;

    hist_kernel<<<(NP + 255) / 256, 256>>>(dens, sp);
    scan_kernel<<<1, 1024>>>();
    scatter_kernel<<<(NP + 255) / 256, 256>>>();
    main_kernel<<<NC, MAINT>>>(v0, v1, v2, v3, W, out);
}